// round 14
// baseline (speedup 1.0000x reference)
#include <cuda_runtime.h>
#include <cuda_fp16.h>
#include <cstdint>

// ---------------------------------------------------------------------------
// CrossNetLayer on GB300 (sm_103a; PTX target compute_103 -> no tcgen05)
//   h = x @ W_enc + b_enc  -> mma.sync fp16 GEMM, fp32 accum.
//   cross layers closed-form, folded into the GEMM epilogue:
//     V_l = W @ w_l ; c_l = b_enc . w_l ; e_l = u_l . w_l ; u4 = sum b_l
//     d_l(row) = x_row . V_l + c_l ;  a <- a + a*d_l + e_l (a0=1)
//     out = a4 * h + u4
// a4 computed inside the GEMM launch by 32 producer CTAs (bn = 16,17).
// GEMM: 64x64 CTA tile, 8 warps (2Mx4N), warp tile 32x16 -> 2048 warps.
// ---------------------------------------------------------------------------

#define BDIM 1024
#define HDIM 1024
#define KDIM 1024
#define DEPTH 4

// Scratch (no cudaMalloc allowed)
__device__ __half  g_x16[BDIM * KDIM];
__device__ __half  g_w16[KDIM * HDIM];   // W in original [k][n] layout, fp16
__device__ float   g_V[DEPTH * KDIM];    // V[l][k] = W[k,:].w_l   (fp32)
__device__ float   g_e[DEPTH];           // e_l = u_l . w_l
__device__ float   g_c[DEPTH];           // c_l = b_enc . w_l
__device__ float   g_u4[HDIM];           // u4 = b0+b1+b2+b3
__device__ float   g_a4[BDIM];           // per-row output scale
__device__ int     g_flag[16];           // per-bm a4 readiness (2 producers each)

// ---------------------------------------------------------------------------
// helpers
// ---------------------------------------------------------------------------
__device__ __forceinline__ uint32_t smem_u32(const void* p) {
    uint32_t a;
    asm("{ .reg .u64 t; cvta.to.shared.u64 t, %1; cvt.u32.u64 %0, t; }"
        : "=r"(a) : "l"(p));
    return a;
}

__device__ __forceinline__ uint32_t swz(uint32_t off) {
    return off ^ ((off >> 3) & 0x70);   // SW128: 16B granule ^= row&7
}

__device__ __forceinline__ void cp_async16(uint32_t smem_addr, const void* gptr) {
    asm volatile("cp.async.cg.shared.global [%0], [%1], 16;"
                 :: "r"(smem_addr), "l"(gptr));
}

__device__ __forceinline__ void ldsm_x4(uint32_t* r, uint32_t addr) {
    asm volatile("ldmatrix.sync.aligned.m8n8.x4.shared.b16 {%0,%1,%2,%3}, [%4];"
                 : "=r"(r[0]), "=r"(r[1]), "=r"(r[2]), "=r"(r[3]) : "r"(addr));
}

__device__ __forceinline__ void ldsm_x4_t(uint32_t* r, uint32_t addr) {
    asm volatile("ldmatrix.sync.aligned.m8n8.x4.trans.shared.b16 {%0,%1,%2,%3}, [%4];"
                 : "=r"(r[0]), "=r"(r[1]), "=r"(r[2]), "=r"(r[3]) : "r"(addr));
}

__device__ __forceinline__ void mma_f16(float* d, const uint32_t* a, const uint32_t* b) {
    asm volatile(
        "mma.sync.aligned.m16n8k16.row.col.f32.f16.f16.f32 "
        "{%0,%1,%2,%3}, {%4,%5,%6,%7}, {%8,%9}, {%0,%1,%2,%3};"
        : "+f"(d[0]), "+f"(d[1]), "+f"(d[2]), "+f"(d[3])
        : "r"(a[0]), "r"(a[1]), "r"(a[2]), "r"(a[3]), "r"(b[0]), "r"(b[1]));
}

__device__ __forceinline__ float dot4(float4 a, float4 b) {
    return a.x * b.x + a.y * b.y + a.z * b.z + a.w * b.w;
}

// ---------------------------------------------------------------------------
// Kernel 1: precompute (769 blocks x 256 threads)
//   blocks [0,256):   x fp32 -> g_x16 (16 floats/thread, 4 batched loads)
//   blocks [256,768): W rows 2b,2b+1 -> g_w16 + V dots
//   block 768:        e_l, c_l, u4, flag reset
// ---------------------------------------------------------------------------
__global__ __launch_bounds__(256, 1) void precompute_kernel(
    const float* __restrict__ x, const float* __restrict__ W,
    const float* __restrict__ b_enc,
    const float* __restrict__ ws, const float* __restrict__ bs)
{
    __shared__ float red[8][8];
    const int bid  = blockIdx.x;
    const int tid  = threadIdx.x;
    const int lane = tid & 31;
    const int wid  = tid >> 5;

    if (bid < 256) {
        const int base = bid * 4096 + tid * 4;
        float4 v[4];
#pragma unroll
        for (int j = 0; j < 4; j++)
            v[j] = *(const float4*)(x + base + j * 1024);
#pragma unroll
        for (int j = 0; j < 4; j++) {
            __half2* d = (__half2*)(g_x16 + base + j * 1024);
            d[0] = __floats2half2_rn(v[j].x, v[j].y);
            d[1] = __floats2half2_rn(v[j].z, v[j].w);
        }
        return;
    }

    if (bid < 768) {
        const int wb = bid - 256;
        const int r0 = wb * 2, r1 = r0 + 1;
        float4 a = *(const float4*)(W + (size_t)r0 * HDIM + tid * 4);
        float4 b = *(const float4*)(W + (size_t)r1 * HDIM + tid * 4);
        float4 wl[4];
#pragma unroll
        for (int l = 0; l < 4; l++)
            wl[l] = *(const float4*)(ws + l * HDIM + tid * 4);

        __half2* d0 = (__half2*)(g_w16 + (size_t)r0 * HDIM + tid * 4);
        d0[0] = __floats2half2_rn(a.x, a.y);
        d0[1] = __floats2half2_rn(a.z, a.w);
        __half2* d1 = (__half2*)(g_w16 + (size_t)r1 * HDIM + tid * 4);
        d1[0] = __floats2half2_rn(b.x, b.y);
        d1[1] = __floats2half2_rn(b.z, b.w);

        float p[4], q[4];
#pragma unroll
        for (int l = 0; l < 4; l++) { p[l] = dot4(a, wl[l]); q[l] = dot4(b, wl[l]); }
#pragma unroll
        for (int o = 16; o > 0; o >>= 1) {
#pragma unroll
            for (int l = 0; l < 4; l++) {
                p[l] += __shfl_xor_sync(0xffffffffu, p[l], o);
                q[l] += __shfl_xor_sync(0xffffffffu, q[l], o);
            }
        }
        if (lane == 0) {
#pragma unroll
            for (int l = 0; l < 4; l++) { red[wid][l] = p[l]; red[wid][4 + l] = q[l]; }
        }
        __syncthreads();
        if (tid == 0) {
#pragma unroll
            for (int l = 0; l < 4; l++) {
                float sA = 0.f, sB = 0.f;
#pragma unroll
                for (int w = 0; w < 8; w++) { sA += red[w][l]; sB += red[w][4 + l]; }
                g_V[l * KDIM + r0] = sA;
                g_V[l * KDIM + r1] = sB;
            }
        }
        return;
    }

    // ---- block 768: e_l, c_l, u4, flag reset ----
    if (tid < 16) g_flag[tid] = 0;
    float r[7];   // c0,c1,c2,c3,e1,e2,e3
#pragma unroll
    for (int i = 0; i < 7; i++) r[i] = 0.f;
#pragma unroll
    for (int j = 0; j < 4; j++) {
        int c = tid * 4 + j;
        float be = b_enc[c];
        float b0 = bs[0 * HDIM + c];
        float b1 = bs[1 * HDIM + c];
        float b2 = bs[2 * HDIM + c];
        float b3 = bs[3 * HDIM + c];
        float w0 = ws[0 * HDIM + c];
        float w1 = ws[1 * HDIM + c];
        float w2 = ws[2 * HDIM + c];
        float w3 = ws[3 * HDIM + c];
        r[0] += be * w0;
        r[1] += be * w1;
        r[2] += be * w2;
        r[3] += be * w3;
        r[4] += b0 * w1;
        r[5] += (b0 + b1) * w2;
        r[6] += (b0 + b1 + b2) * w3;
        g_u4[c] = b0 + b1 + b2 + b3;
    }
#pragma unroll
    for (int o = 16; o > 0; o >>= 1)
#pragma unroll
        for (int i = 0; i < 7; i++)
            r[i] += __shfl_xor_sync(0xffffffffu, r[i], o);
    if (lane == 0) {
#pragma unroll
        for (int i = 0; i < 7; i++) red[wid][i] = r[i];
    }
    __syncthreads();
    if (tid == 0) {
        float s[7];
#pragma unroll
        for (int i = 0; i < 7; i++) {
            s[i] = 0.f;
#pragma unroll
            for (int w = 0; w < 8; w++) s[i] += red[w][i];
        }
        g_c[0] = s[0]; g_c[1] = s[1]; g_c[2] = s[2]; g_c[3] = s[3];
        g_e[0] = 0.0f; g_e[1] = s[4]; g_e[2] = s[5]; g_e[3] = s[6];
    }
}

// ---------------------------------------------------------------------------
// Kernel 2: GEMM + integrated a4 producers + fused cross epilogue.
// Grid (18,16), 256 threads, __launch_bounds__(256,2) -> 2 CTAs/SM:
//   bn in [0,16): GEMM CTA (64x64 tile, 8 warps of 32x16)
//   bn in {16,17}: a4 producer for rows bm*64 + (bn-16)*32 + [0,32)
// ---------------------------------------------------------------------------
#define GBM 64
#define GBN 64
#define GKC 128
#define NCHUNK (KDIM / GKC)     // 8

#define SUB_A 0
#define SUB_B 16384
#define STAGE_BYTES 32768
#define GEMM_SMEM (2 * STAGE_BYTES)   // 65536

__global__ __launch_bounds__(256, 2) void gemm_mma_kernel(
    const float* __restrict__ bias, const float* __restrict__ x,
    float* __restrict__ out)
{
    extern __shared__ char smem[];
    const int tid  = threadIdx.x;     // 0..255
    const int wid  = tid >> 5;        // 0..7
    const int lane = tid & 31;
    const int bn   = blockIdx.x;      // 0..17
    const int bm   = blockIdx.y;      // 0..15

    if (bn >= 16) {
        // ================= a4 producer CTA =================
        float4* sV = (float4*)smem;
        const float4* gV = (const float4*)g_V;
#pragma unroll
        for (int i = 0; i < 4; i++)
            sV[tid + i * 256] = gV[tid + i * 256];
        __syncthreads();

        float cc[4], ee[4];
#pragma unroll
        for (int l = 0; l < 4; l++) { cc[l] = g_c[l]; ee[l] = g_e[l]; }

        const int rbase = bm * 64 + (bn - 16) * 32 + wid * 4;
#pragma unroll
        for (int it = 0; it < 4; it++) {
            const int r = rbase + it;
            const float4* xr = (const float4*)(x + (size_t)r * KDIM);
            float4 xv[8];
#pragma unroll
            for (int j = 0; j < 8; j++)
                xv[j] = xr[lane + j * 32];
            float p[4] = {0.f, 0.f, 0.f, 0.f};
#pragma unroll
            for (int j = 0; j < 8; j++) {
#pragma unroll
                for (int l = 0; l < 4; l++)
                    p[l] += dot4(xv[j], sV[l * 256 + lane + j * 32]);
            }
#pragma unroll
            for (int o = 16; o > 0; o >>= 1) {
#pragma unroll
                for (int l = 0; l < 4; l++)
                    p[l] += __shfl_xor_sync(0xffffffffu, p[l], o);
            }
            if (lane == 0) {
                float a4 = 1.0f;
#pragma unroll
                for (int l = 0; l < 4; l++) {
                    float d = p[l] + cc[l];
                    a4 += a4 * d + ee[l];
                }
                g_a4[r] = a4;
            }
        }
        __threadfence();
        __syncthreads();
        if (tid == 0) atomicAdd(&g_flag[bm], 1);
        return;
    }

    // ================= GEMM CTA =================
    const uint32_t sb = smem_u32(smem);
    const int warp_m = wid >> 2;      // 0..1 -> M offset 32*warp_m
    const int warp_n = wid & 3;       // 0..3 -> N offset 16*warp_n

    // ---- A load addressing: 64 rows x 16 granules = 1024, 4 per thread ----
    const char* pA[4]; uint32_t offA[4];
#pragma unroll
    for (int it = 0; it < 4; ++it) {
        int idx = tid + it * 256;
        int row = idx >> 4;          // 0..63 (m)
        int g   = idx & 15;          // 16B granule within 256B k-row
        size_t gb = ((size_t)(bm * GBM + row) * KDIM) * 2 + g * 16;
        pA[it] = (const char*)g_x16 + gb;
        offA[it] = (uint32_t)(g >> 3) * 8192 + swz(row * 128 + (g & 7) * 16);
    }
    // ---- B load addressing: 128 k-rows x 8 granules = 1024, 4 per thread ----
    const char* pB[4]; uint32_t offB[4];
#pragma unroll
    for (int it = 0; it < 4; ++it) {
        int idx = tid + it * 256;
        int row = idx >> 3;          // 0..127 (k)
        int g   = idx & 7;           // 16B granule within 128B n-row
        pB[it] = (const char*)g_w16 + (size_t)row * 2048 + bn * 128 + g * 16;
        offB[it] = swz(row * 128 + g * 16);
    }

    // ---- ldmatrix per-lane offset components ----
    const int a_row_l = lane & 15;
    const int a_kb_l  = (lane >> 4) << 4;
    const int b_krow_l = (lane & 7) + ((lane >> 3) & 1) * 8;
    const int b_nb_l   = (lane >> 4) << 4;    // +16 bytes = +8 n-cols

    float acc[2][2][4];
#pragma unroll
    for (int mi = 0; mi < 2; mi++)
#pragma unroll
        for (int ni = 0; ni < 2; ni++)
#pragma unroll
            for (int j = 0; j < 4; j++) acc[mi][ni][j] = 0.0f;

    // ---- prologue: preload chunk 0 into stage 0 ----
#pragma unroll
    for (int it = 0; it < 4; ++it) {
        cp_async16(sb + SUB_A + offA[it], pA[it]);
        cp_async16(sb + SUB_B + offB[it], pB[it]);
    }
    asm volatile("cp.async.commit_group;" ::: "memory");

    for (int c = 0; c < NCHUNK; ++c) {
        asm volatile("cp.async.wait_group 0;" ::: "memory");
        __syncthreads();

        if (c + 1 < NCHUNK) {
            uint32_t dst = sb + ((c + 1) & 1) * STAGE_BYTES;
            size_t goA = (size_t)(c + 1) * 256;        // +128 k fp16 along row
            size_t goB = (size_t)(c + 1) * 262144;     // +128 k-rows of 2048B
#pragma unroll
            for (int it = 0; it < 4; ++it) {
                cp_async16(dst + SUB_A + offA[it], pA[it] + goA);
                cp_async16(dst + SUB_B + offB[it], pB[it] + goB);
            }
            asm volatile("cp.async.commit_group;" ::: "memory");
        }

        const uint32_t base = sb + (c & 1) * STAGE_BYTES;
#pragma unroll
        for (int sub = 0; sub < 2; sub++) {
            const uint32_t baseA = base + SUB_A + sub * 8192;
            const uint32_t baseB = base + SUB_B;
            const int ksub = sub * 64;
#pragma unroll
            for (int kk = 0; kk < 4; kk++) {
                uint32_t RA[2][4], RB[4];
#pragma unroll
                for (int mi = 0; mi < 2; mi++) {
                    int row = warp_m * 32 + mi * 16 + a_row_l;
                    uint32_t off = swz(row * 128 + kk * 32 + a_kb_l);
                    ldsm_x4(RA[mi], baseA + off);
                }
                {
                    int krow = ksub + kk * 16 + b_krow_l;
                    int nb   = (warp_n * 16) * 2 + b_nb_l;
                    uint32_t off = swz(krow * 128 + nb);
                    ldsm_x4_t(RB, baseB + off);
                }
#pragma unroll
                for (int mi = 0; mi < 2; mi++)
#pragma unroll
                    for (int ni = 0; ni < 2; ni++)
                        mma_f16(acc[mi][ni], RA[mi], &RB[2 * ni]);
            }
        }
        __syncthreads();
    }

    // ---- wait for a4 producers of this bm (long since done in practice) ----
    if (tid == 0) {
        while (atomicAdd(&g_flag[bm], 0) < 2) { }
    }
    __syncthreads();
    __threadfence();

    // ---- fused epilogue: out = a4(row) * (acc + bias) + u4(col) ----
    const int g = lane >> 2;
    const int t = lane & 3;
#pragma unroll
    for (int mi = 0; mi < 2; mi++) {
        int row0 = bm * GBM + warp_m * 32 + mi * 16 + g;
        float aR0 = g_a4[row0];
        float aR8 = g_a4[row0 + 8];
#pragma unroll
        for (int ni = 0; ni < 2; ni++) {
            int col = bn * GBN + warp_n * 16 + ni * 8 + t * 2;
            float b0 = bias[col];
            float b1 = bias[col + 1];
            float u0 = g_u4[col];
            float u1 = g_u4[col + 1];
            float2 v0, v1;
            v0.x = fmaf(aR0, acc[mi][ni][0] + b0, u0);
            v0.y = fmaf(aR0, acc[mi][ni][1] + b1, u1);
            v1.x = fmaf(aR8, acc[mi][ni][2] + b0, u0);
            v1.y = fmaf(aR8, acc[mi][ni][3] + b1, u1);
            *(float2*)(out + (size_t)row0 * HDIM + col) = v0;
            *(float2*)(out + (size_t)(row0 + 8) * HDIM + col) = v1;
        }
    }
}

// ---------------------------------------------------------------------------
extern "C" void kernel_launch(void* const* d_in, const int* in_sizes, int n_in,
                              void* d_out, int out_size)
{
    const float* x     = (const float*)d_in[0];
    const float* W_enc = (const float*)d_in[1];
    const float* b_enc = (const float*)d_in[2];
    const float* ws    = (const float*)d_in[3];
    const float* bs    = (const float*)d_in[4];
    float* out = (float*)d_out;

    cudaFuncSetAttribute(gemm_mma_kernel,
                         cudaFuncAttributeMaxDynamicSharedMemorySize, GEMM_SMEM);

    precompute_kernel<<<769, 256>>>(x, W_enc, b_enc, ws, bs);
    gemm_mma_kernel<<<dim3(18, 16), 256, GEMM_SMEM>>>(b_enc, x, out);
}

// round 15
// speedup vs baseline: 1.0863x; 1.0863x over previous
#include <cuda_runtime.h>
#include <cuda_fp16.h>
#include <cstdint>

// ---------------------------------------------------------------------------
// CrossNetLayer on GB300 (sm_103a; PTX target compute_103 -> no tcgen05)
//   h = x @ W_enc + b_enc  -> mma.sync fp16 GEMM, fp32 accum.
//   cross layers closed-form, folded into the GEMM epilogue:
//     V_l = W @ w_l ; c_l = b_enc . w_l ; e_l = u_l . w_l ; u4 = sum b_l
//     d_l(row) = x_row . V_l + c_l ;  a <- a + a*d_l + e_l (a0=1)
//     out = a4 * h + u4
// a4 computed inside the GEMM launch by 16 producer CTAs (bn = 16,17).
// GEMM: BM=128, BN=64 CTA tile, 8 warps (4Mx2N), warp tile 32x32.
// Grid (18,8) = 144 CTAs -> exactly one CTA per SM.
// ---------------------------------------------------------------------------

#define BDIM 1024
#define HDIM 1024
#define KDIM 1024
#define DEPTH 4

// Scratch (no cudaMalloc allowed)
__device__ __half  g_x16[BDIM * KDIM];
__device__ __half  g_w16[KDIM * HDIM];   // W in original [k][n] layout, fp16
__device__ float   g_V[DEPTH * KDIM];    // V[l][k] = W[k,:].w_l   (fp32)
__device__ float   g_e[DEPTH];           // e_l = u_l . w_l
__device__ float   g_c[DEPTH];           // c_l = b_enc . w_l
__device__ float   g_u4[HDIM];           // u4 = b0+b1+b2+b3
__device__ float   g_a4[BDIM];           // per-row output scale
__device__ int     g_flag[8];            // per-bm a4 readiness (2 producers each)

// ---------------------------------------------------------------------------
// helpers
// ---------------------------------------------------------------------------
__device__ __forceinline__ uint32_t smem_u32(const void* p) {
    uint32_t a;
    asm("{ .reg .u64 t; cvta.to.shared.u64 t, %1; cvt.u32.u64 %0, t; }"
        : "=r"(a) : "l"(p));
    return a;
}

__device__ __forceinline__ uint32_t swz(uint32_t off) {
    return off ^ ((off >> 3) & 0x70);   // SW128: 16B granule ^= row&7
}

__device__ __forceinline__ void cp_async16(uint32_t smem_addr, const void* gptr) {
    asm volatile("cp.async.cg.shared.global [%0], [%1], 16;"
                 :: "r"(smem_addr), "l"(gptr));
}

__device__ __forceinline__ void ldsm_x4(uint32_t* r, uint32_t addr) {
    asm volatile("ldmatrix.sync.aligned.m8n8.x4.shared.b16 {%0,%1,%2,%3}, [%4];"
                 : "=r"(r[0]), "=r"(r[1]), "=r"(r[2]), "=r"(r[3]) : "r"(addr));
}

__device__ __forceinline__ void ldsm_x4_t(uint32_t* r, uint32_t addr) {
    asm volatile("ldmatrix.sync.aligned.m8n8.x4.trans.shared.b16 {%0,%1,%2,%3}, [%4];"
                 : "=r"(r[0]), "=r"(r[1]), "=r"(r[2]), "=r"(r[3]) : "r"(addr));
}

__device__ __forceinline__ void mma_f16(float* d, const uint32_t* a, const uint32_t* b) {
    asm volatile(
        "mma.sync.aligned.m16n8k16.row.col.f32.f16.f16.f32 "
        "{%0,%1,%2,%3}, {%4,%5,%6,%7}, {%8,%9}, {%0,%1,%2,%3};"
        : "+f"(d[0]), "+f"(d[1]), "+f"(d[2]), "+f"(d[3])
        : "r"(a[0]), "r"(a[1]), "r"(a[2]), "r"(a[3]), "r"(b[0]), "r"(b[1]));
}

__device__ __forceinline__ float dot4(float4 a, float4 b) {
    return a.x * b.x + a.y * b.y + a.z * b.z + a.w * b.w;
}

// ---------------------------------------------------------------------------
// Kernel 1: precompute (769 blocks x 256 threads)
//   blocks [0,256):   x fp32 -> g_x16 (16 floats/thread, 4 batched loads)
//   blocks [256,768): W rows 2b,2b+1 -> g_w16 + V dots
//   block 768:        e_l, c_l, u4, flag reset
// ---------------------------------------------------------------------------
__global__ __launch_bounds__(256, 1) void precompute_kernel(
    const float* __restrict__ x, const float* __restrict__ W,
    const float* __restrict__ b_enc,
    const float* __restrict__ ws, const float* __restrict__ bs)
{
    __shared__ float red[8][8];
    const int bid  = blockIdx.x;
    const int tid  = threadIdx.x;
    const int lane = tid & 31;
    const int wid  = tid >> 5;

    if (bid < 256) {
        const int base = bid * 4096 + tid * 4;
        float4 v[4];
#pragma unroll
        for (int j = 0; j < 4; j++)
            v[j] = *(const float4*)(x + base + j * 1024);
#pragma unroll
        for (int j = 0; j < 4; j++) {
            __half2* d = (__half2*)(g_x16 + base + j * 1024);
            d[0] = __floats2half2_rn(v[j].x, v[j].y);
            d[1] = __floats2half2_rn(v[j].z, v[j].w);
        }
        return;
    }

    if (bid < 768) {
        const int wb = bid - 256;
        const int r0 = wb * 2, r1 = r0 + 1;
        float4 a = *(const float4*)(W + (size_t)r0 * HDIM + tid * 4);
        float4 b = *(const float4*)(W + (size_t)r1 * HDIM + tid * 4);
        float4 wl[4];
#pragma unroll
        for (int l = 0; l < 4; l++)
            wl[l] = *(const float4*)(ws + l * HDIM + tid * 4);

        __half2* d0 = (__half2*)(g_w16 + (size_t)r0 * HDIM + tid * 4);
        d0[0] = __floats2half2_rn(a.x, a.y);
        d0[1] = __floats2half2_rn(a.z, a.w);
        __half2* d1 = (__half2*)(g_w16 + (size_t)r1 * HDIM + tid * 4);
        d1[0] = __floats2half2_rn(b.x, b.y);
        d1[1] = __floats2half2_rn(b.z, b.w);

        float p[4], q[4];
#pragma unroll
        for (int l = 0; l < 4; l++) { p[l] = dot4(a, wl[l]); q[l] = dot4(b, wl[l]); }
#pragma unroll
        for (int o = 16; o > 0; o >>= 1) {
#pragma unroll
            for (int l = 0; l < 4; l++) {
                p[l] += __shfl_xor_sync(0xffffffffu, p[l], o);
                q[l] += __shfl_xor_sync(0xffffffffu, q[l], o);
            }
        }
        if (lane == 0) {
#pragma unroll
            for (int l = 0; l < 4; l++) { red[wid][l] = p[l]; red[wid][4 + l] = q[l]; }
        }
        __syncthreads();
        if (tid == 0) {
#pragma unroll
            for (int l = 0; l < 4; l++) {
                float sA = 0.f, sB = 0.f;
#pragma unroll
                for (int w = 0; w < 8; w++) { sA += red[w][l]; sB += red[w][4 + l]; }
                g_V[l * KDIM + r0] = sA;
                g_V[l * KDIM + r1] = sB;
            }
        }
        return;
    }

    // ---- block 768: e_l, c_l, u4, flag reset ----
    if (tid < 8) g_flag[tid] = 0;
    float r[7];   // c0,c1,c2,c3,e1,e2,e3
#pragma unroll
    for (int i = 0; i < 7; i++) r[i] = 0.f;
#pragma unroll
    for (int j = 0; j < 4; j++) {
        int c = tid * 4 + j;
        float be = b_enc[c];
        float b0 = bs[0 * HDIM + c];
        float b1 = bs[1 * HDIM + c];
        float b2 = bs[2 * HDIM + c];
        float b3 = bs[3 * HDIM + c];
        float w0 = ws[0 * HDIM + c];
        float w1 = ws[1 * HDIM + c];
        float w2 = ws[2 * HDIM + c];
        float w3 = ws[3 * HDIM + c];
        r[0] += be * w0;
        r[1] += be * w1;
        r[2] += be * w2;
        r[3] += be * w3;
        r[4] += b0 * w1;
        r[5] += (b0 + b1) * w2;
        r[6] += (b0 + b1 + b2) * w3;
        g_u4[c] = b0 + b1 + b2 + b3;
    }
#pragma unroll
    for (int o = 16; o > 0; o >>= 1)
#pragma unroll
        for (int i = 0; i < 7; i++)
            r[i] += __shfl_xor_sync(0xffffffffu, r[i], o);
    if (lane == 0) {
#pragma unroll
        for (int i = 0; i < 7; i++) red[wid][i] = r[i];
    }
    __syncthreads();
    if (tid == 0) {
        float s[7];
#pragma unroll
        for (int i = 0; i < 7; i++) {
            s[i] = 0.f;
#pragma unroll
            for (int w = 0; w < 8; w++) s[i] += red[w][i];
        }
        g_c[0] = s[0]; g_c[1] = s[1]; g_c[2] = s[2]; g_c[3] = s[3];
        g_e[0] = 0.0f; g_e[1] = s[4]; g_e[2] = s[5]; g_e[3] = s[6];
    }
}

// ---------------------------------------------------------------------------
// Kernel 2: GEMM + integrated a4 producers + fused cross epilogue.
// Grid (18,8), 256 threads, 1 CTA/SM (144 CTAs on 148 SMs):
//   bn in [0,16): GEMM CTA (128x64 tile, 8 warps of 32x32)
//   bn in {16,17}: a4 producer for rows bm*128 + (bn-16)*64 + [0,64)
// ---------------------------------------------------------------------------
#define GBM 128
#define GBN 64
#define GKC 128
#define NCHUNK (KDIM / GKC)     // 8

// stage layout (bytes): A[2][16384] sub-tiles, B[16384]
#define SUB_A 0
#define SUB_B 32768
#define STAGE_BYTES 49152
#define GEMM_SMEM (2 * STAGE_BYTES)   // 98304

__global__ __launch_bounds__(256, 1) void gemm_mma_kernel(
    const float* __restrict__ bias, const float* __restrict__ x,
    float* __restrict__ out)
{
    extern __shared__ char smem[];
    const int tid  = threadIdx.x;     // 0..255
    const int wid  = tid >> 5;        // 0..7
    const int lane = tid & 31;
    const int bn   = blockIdx.x;      // 0..17
    const int bm   = blockIdx.y;      // 0..7

    if (bn >= 16) {
        // ================= a4 producer CTA (64 rows) =================
        float4* sV = (float4*)smem;
        const float4* gV = (const float4*)g_V;
#pragma unroll
        for (int i = 0; i < 4; i++)
            sV[tid + i * 256] = gV[tid + i * 256];
        __syncthreads();

        float cc[4], ee[4];
#pragma unroll
        for (int l = 0; l < 4; l++) { cc[l] = g_c[l]; ee[l] = g_e[l]; }

        const int rbase = bm * 128 + (bn - 16) * 64 + wid * 8;
#pragma unroll
        for (int it = 0; it < 8; it++) {
            const int r = rbase + it;
            const float4* xr = (const float4*)(x + (size_t)r * KDIM);
            float4 xv[8];
#pragma unroll
            for (int j = 0; j < 8; j++)
                xv[j] = xr[lane + j * 32];
            float p[4] = {0.f, 0.f, 0.f, 0.f};
#pragma unroll
            for (int j = 0; j < 8; j++) {
#pragma unroll
                for (int l = 0; l < 4; l++)
                    p[l] += dot4(xv[j], sV[l * 256 + lane + j * 32]);
            }
#pragma unroll
            for (int o = 16; o > 0; o >>= 1) {
#pragma unroll
                for (int l = 0; l < 4; l++)
                    p[l] += __shfl_xor_sync(0xffffffffu, p[l], o);
            }
            if (lane == 0) {
                float a4 = 1.0f;
#pragma unroll
                for (int l = 0; l < 4; l++) {
                    float d = p[l] + cc[l];
                    a4 += a4 * d + ee[l];
                }
                g_a4[r] = a4;
            }
        }
        __threadfence();
        __syncthreads();
        if (tid == 0) atomicAdd(&g_flag[bm], 1);
        return;
    }

    // ================= GEMM CTA =================
    const uint32_t sb = smem_u32(smem);
    const int warp_m = wid >> 1;      // 0..3 -> M offset 32*warp_m
    const int warp_n = wid & 1;       // 0..1 -> N offset 32*warp_n

    // ---- A load addressing: 128 rows x 16 granules = 2048, 8 per thread ----
    const char* pA[8]; uint32_t offA[8];
#pragma unroll
    for (int it = 0; it < 8; ++it) {
        int idx = tid + it * 256;
        int row = idx >> 4;          // 0..127 (m)
        int g   = idx & 15;          // 16B granule within 256B k-row
        size_t gb = ((size_t)(bm * GBM + row) * KDIM) * 2 + g * 16;
        pA[it] = (const char*)g_x16 + gb;
        offA[it] = (uint32_t)(g >> 3) * 16384 + swz(row * 128 + (g & 7) * 16);
    }
    // ---- B load addressing: 128 k-rows x 8 granules = 1024, 4 per thread ----
    const char* pB[4]; uint32_t offB[4];
#pragma unroll
    for (int it = 0; it < 4; ++it) {
        int idx = tid + it * 256;
        int row = idx >> 3;          // 0..127 (k)
        int g   = idx & 7;           // 16B granule within 128B n-row
        pB[it] = (const char*)g_w16 + (size_t)row * 2048 + bn * 128 + g * 16;
        offB[it] = swz(row * 128 + g * 16);
    }

    // ---- ldmatrix per-lane offset components ----
    const int a_row_l = lane & 15;
    const int a_kb_l  = (lane >> 4) << 4;
    const int b_krow_l = (lane & 7) + ((lane >> 3) & 1) * 8;
    const int b_nb_l   = (lane >> 4) << 4;    // +16 bytes = +8 n-cols

    float acc[2][4][4];
#pragma unroll
    for (int mi = 0; mi < 2; mi++)
#pragma unroll
        for (int ni = 0; ni < 4; ni++)
#pragma unroll
            for (int j = 0; j < 4; j++) acc[mi][ni][j] = 0.0f;

    // ---- prologue: preload chunk 0 into stage 0 ----
#pragma unroll
    for (int it = 0; it < 8; ++it)
        cp_async16(sb + SUB_A + offA[it], pA[it]);
#pragma unroll
    for (int it = 0; it < 4; ++it)
        cp_async16(sb + SUB_B + offB[it], pB[it]);
    asm volatile("cp.async.commit_group;" ::: "memory");

    for (int c = 0; c < NCHUNK; ++c) {
        asm volatile("cp.async.wait_group 0;" ::: "memory");
        __syncthreads();

        if (c + 1 < NCHUNK) {
            uint32_t dst = sb + ((c + 1) & 1) * STAGE_BYTES;
            size_t goA = (size_t)(c + 1) * 256;        // +128 k fp16 along row
            size_t goB = (size_t)(c + 1) * 262144;     // +128 k-rows of 2048B
#pragma unroll
            for (int it = 0; it < 8; ++it)
                cp_async16(dst + SUB_A + offA[it], pA[it] + goA);
#pragma unroll
            for (int it = 0; it < 4; ++it)
                cp_async16(dst + SUB_B + offB[it], pB[it] + goB);
            asm volatile("cp.async.commit_group;" ::: "memory");
        }

        const uint32_t base = sb + (c & 1) * STAGE_BYTES;
#pragma unroll
        for (int sub = 0; sub < 2; sub++) {
            const uint32_t baseA = base + SUB_A + sub * 16384;
            const uint32_t baseB = base + SUB_B;
            const int ksub = sub * 64;
#pragma unroll
            for (int kk = 0; kk < 4; kk++) {
                uint32_t RA[2][4], RB[8];
#pragma unroll
                for (int mi = 0; mi < 2; mi++) {
                    int row = warp_m * 32 + mi * 16 + a_row_l;
                    uint32_t off = swz(row * 128 + kk * 32 + a_kb_l);
                    ldsm_x4(RA[mi], baseA + off);
                }
#pragma unroll
                for (int p = 0; p < 2; p++) {
                    int krow = ksub + kk * 16 + b_krow_l;
                    int nb   = (warp_n * 32 + p * 16) * 2 + b_nb_l;
                    uint32_t off = swz(krow * 128 + nb);
                    ldsm_x4_t(&RB[4 * p], baseB + off);
                }
#pragma unroll
                for (int mi = 0; mi < 2; mi++)
#pragma unroll
                    for (int ni = 0; ni < 4; ni++)
                        mma_f16(acc[mi][ni], RA[mi], &RB[2 * ni]);
            }
        }
        __syncthreads();
    }

    // ---- wait for a4 producers of this bm (long since done in practice) ----
    if (tid == 0) {
        while (atomicAdd(&g_flag[bm], 0) < 2) { }
    }
    __syncthreads();
    __threadfence();

    // ---- fused epilogue: out = a4(row) * (acc + bias) + u4(col) ----
    const int g = lane >> 2;
    const int t = lane & 3;
#pragma unroll
    for (int mi = 0; mi < 2; mi++) {
        int row0 = bm * GBM + warp_m * 32 + mi * 16 + g;
        float aR0 = g_a4[row0];
        float aR8 = g_a4[row0 + 8];
#pragma unroll
        for (int ni = 0; ni < 4; ni++) {
            int col = bn * GBN + warp_n * 32 + ni * 8 + t * 2;
            float b0 = bias[col];
            float b1 = bias[col + 1];
            float u0 = g_u4[col];
            float u1 = g_u4[col + 1];
            float2 v0, v1;
            v0.x = fmaf(aR0, acc[mi][ni][0] + b0, u0);
            v0.y = fmaf(aR0, acc[mi][ni][1] + b1, u1);
            v1.x = fmaf(aR8, acc[mi][ni][2] + b0, u0);
            v1.y = fmaf(aR8, acc[mi][ni][3] + b1, u1);
            *(float2*)(out + (size_t)row0 * HDIM + col) = v0;
            *(float2*)(out + (size_t)(row0 + 8) * HDIM + col) = v1;
        }
    }
}

// ---------------------------------------------------------------------------
extern "C" void kernel_launch(void* const* d_in, const int* in_sizes, int n_in,
                              void* d_out, int out_size)
{
    const float* x     = (const float*)d_in[0];
    const float* W_enc = (const float*)d_in[1];
    const float* b_enc = (const float*)d_in[2];
    const float* ws    = (const float*)d_in[3];
    const float* bs    = (const float*)d_in[4];
    float* out = (float*)d_out;

    cudaFuncSetAttribute(gemm_mma_kernel,
                         cudaFuncAttributeMaxDynamicSharedMemorySize, GEMM_SMEM);

    precompute_kernel<<<769, 256>>>(x, W_enc, b_enc, ws, bs);
    gemm_mma_kernel<<<dim3(18, 8), 256, GEMM_SMEM>>>(b_enc, x, out);
}